// round 8
// baseline (speedup 1.0000x reference)
#include <cuda_runtime.h>
#include <cuda_fp16.h>
#include <cstdint>

// ---------------- problem constants ----------------
#define M_TOTAL 8192
#define N_TOTAL 4096
#define K_IN    4096

#define BM 128
#define BN 128
#define BKS 64                        // fp16 k-elems per stage
#define NK (K_IN / BKS)               // 64
#define STAGES 3
#define PITCH 72                      // smem row pitch in fp16 (64 data + 8 pad)
#define TILE_BYTES (128 * PITCH * 2)  // 18432 B per (A or B) stage tile
#define STAGE_BYTES (2 * TILE_BYTES)  // 36864
#define SMEM_BYTES (STAGES * STAGE_BYTES)  // 110592 (x2 CTAs = 221KB < 228KB)

#define TAU 0.125f
#define CAP (1u << 22)

// ---------------- scratch ----------------
__device__ __half g_A[(size_t)M_TOTAL * K_IN];  // hi limb: fl16(x)
__device__ __half g_W[(size_t)N_TOTAL * K_IN];  // sign(W) as fp16
__device__ unsigned g_cnt;
__device__ uint2 g_list[CAP];

// ---------------- helpers ----------------
static __device__ __forceinline__ void cpa16(uint32_t dst, const void* src) {
    asm volatile("cp.async.cg.shared.global [%0], [%1], 16;" :: "r"(dst), "l"(src));
}
static __device__ __forceinline__ void ldsm4(uint32_t* r, uint32_t addr) {
    asm volatile("ldmatrix.sync.aligned.m8n8.x4.shared.b16 {%0,%1,%2,%3}, [%4];"
                 : "=r"(r[0]), "=r"(r[1]), "=r"(r[2]), "=r"(r[3]) : "r"(addr));
}
static __device__ __forceinline__ void mma16816(float* c, const uint32_t* a, const uint32_t* b) {
    asm volatile(
        "mma.sync.aligned.m16n8k16.row.col.f32.f16.f16.f32 "
        "{%0,%1,%2,%3}, {%4,%5,%6,%7}, {%8,%9}, {%0,%1,%2,%3};"
        : "+f"(c[0]), "+f"(c[1]), "+f"(c[2]), "+f"(c[3])
        : "r"(a[0]), "r"(a[1]), "r"(a[2]), "r"(a[3]), "r"(b[0]), "r"(b[1]));
}
static __device__ __forceinline__ float sgnf(float z) {
    return (z > 0.f) ? 1.f : ((z < 0.f) ? -1.f : 0.f);
}

// ---------------- prep kernels ----------------
__global__ void zero_cnt() { g_cnt = 0u; }

__global__ void prep_x(const float* __restrict__ x) {
    const int t   = blockIdx.x * blockDim.x + threadIdx.x;
    const int row = blockIdx.y;
    const int col = t * 4;
    float4 v = *reinterpret_cast<const float4*>(&x[(size_t)row * K_IN + col]);
    float vv[4] = {v.x, v.y, v.z, v.w};
    __half hi[4];
    #pragma unroll
    for (int j = 0; j < 4; j++) hi[j] = __float2half_rn(vv[j]);
    *reinterpret_cast<uint2*>(&g_A[(size_t)row * K_IN + col]) =
        *reinterpret_cast<uint2*>(hi);
}

__global__ void prep_w(const float* __restrict__ w) {
    const size_t idx = (size_t)blockIdx.x * blockDim.x + threadIdx.x;
    float4 v = *reinterpret_cast<const float4*>(&w[idx * 4]);
    float vv[4] = {v.x, v.y, v.z, v.w};
    __half s[4];
    #pragma unroll
    for (int j = 0; j < 4; j++) s[j] = __float2half_rn(sgnf(vv[j]));
    reinterpret_cast<uint2*>(g_W)[idx] = *reinterpret_cast<uint2*>(s);
}

// ---------------- GEMM kernel: 128 threads, 4 warps, warp tile 64x64 ----------------
__global__ void __launch_bounds__(128, 2)
binlin_gemm(const float* __restrict__ bias, float* __restrict__ out) {
    extern __shared__ __align__(16) char smem[];
    const uint32_t su = (uint32_t)__cvta_generic_to_shared(smem);

    const int tid  = threadIdx.x;
    const int wid  = tid >> 5;
    const int lane = tid & 31;
    const int wm = (wid >> 1) * 64;   // 0 or 64
    const int wn = (wid & 1) * 64;    // 0 or 64

    const int m_base = blockIdx.y * BM;
    const int n_base = blockIdx.x * BN;

    float acc[4][8][4];
    #pragma unroll
    for (int mi = 0; mi < 4; mi++)
        #pragma unroll
        for (int ni = 0; ni < 8; ni++)
            #pragma unroll
            for (int j = 0; j < 4; j++) acc[mi][ni][j] = 0.f;

    const int a_row_off = (lane & 7) + ((lane >> 3) & 1) * 8;
    const int a_col_off = (lane >> 4) * 8;
    const int b_row_off = (lane & 7) + (lane >> 4) * 8;
    const int b_col_off = ((lane >> 3) & 1) * 8;

    // stage layout: [A tile | B tile]; 1024 16B-chunks per tile
    auto load_stage = [&](int s, int kk) {
        const uint32_t abase = su + s * STAGE_BYTES;
        const uint32_t bbase = abase + TILE_BYTES;
        const int ka = kk * BKS;
        #pragma unroll
        for (int i = 0; i < 8; i++) {
            const int cid = tid + i * 128;        // 0..1023
            const int row = cid >> 3;             // 0..127
            const int c   = cid & 7;              // 16B chunk
            cpa16(abase + row * (PITCH * 2) + c * 16,
                  &g_A[(size_t)(m_base + row) * K_IN + ka + c * 8]);
            cpa16(bbase + row * (PITCH * 2) + c * 16,
                  &g_W[(size_t)(n_base + row) * K_IN + ka + c * 8]);
        }
    };

    auto compute_stage = [&](int s) {
        const uint32_t abase = su + s * STAGE_BYTES;
        const uint32_t bbase = abase + TILE_BYTES;
        #pragma unroll
        for (int ks = 0; ks < 4; ks++) {
            uint32_t a[4][4];
            uint32_t b[8][2];
            #pragma unroll
            for (int mi = 0; mi < 4; mi++) {
                uint32_t addr = abase +
                    ((wm + mi * 16 + a_row_off) * PITCH + ks * 16 + a_col_off) * 2;
                ldsm4(a[mi], addr);
            }
            #pragma unroll
            for (int p = 0; p < 4; p++) {
                uint32_t t[4];
                uint32_t addr = bbase +
                    ((wn + p * 16 + b_row_off) * PITCH + ks * 16 + b_col_off) * 2;
                ldsm4(t, addr);
                b[2 * p + 0][0] = t[0]; b[2 * p + 0][1] = t[1];
                b[2 * p + 1][0] = t[2]; b[2 * p + 1][1] = t[3];
            }
            #pragma unroll
            for (int mi = 0; mi < 4; mi++)
                #pragma unroll
                for (int ni = 0; ni < 8; ni++)
                    mma16816(acc[mi][ni], a[mi], b[ni]);
        }
    };

    // ---- prologue ----
    #pragma unroll
    for (int s = 0; s < STAGES - 1; s++) {
        load_stage(s, s);
        asm volatile("cp.async.commit_group;");
    }

    // ---- mainloop: one sync per iteration ----
    for (int kk = 0; kk < NK; kk++) {
        asm volatile("cp.async.wait_group %0;" :: "n"(STAGES - 2));
        __syncthreads();
        const int nx = kk + STAGES - 1;
        if (nx < NK) load_stage(nx % STAGES, nx);
        asm volatile("cp.async.commit_group;");
        compute_stage(kk % STAGES);
    }

    // ---- epilogue ----
    #pragma unroll
    for (int mi = 0; mi < 4; mi++) {
        #pragma unroll
        for (int ni = 0; ni < 8; ni++) {
            const int r = m_base + wm + mi * 16 + (lane >> 2);
            const int c = n_base + wn + ni * 8 + (lane & 3) * 2;
            const float b0 = bias[c];
            const float b1 = bias[c + 1];
            float z[4];
            z[0] = acc[mi][ni][0] + b0;
            z[1] = acc[mi][ni][1] + b1;
            z[2] = acc[mi][ni][2] + b0;
            z[3] = acc[mi][ni][3] + b1;
            float2 v0, v1;
            v0.x = sgnf(z[0]); v0.y = sgnf(z[1]);
            v1.x = sgnf(z[2]); v1.y = sgnf(z[3]);
            *reinterpret_cast<float2*>(&out[(size_t)r * N_TOTAL + c]) = v0;
            *reinterpret_cast<float2*>(&out[(size_t)(r + 8) * N_TOTAL + c]) = v1;
            #pragma unroll
            for (int j = 0; j < 4; j++) {
                if (fabsf(z[j]) < TAU) {
                    const int rr = r + (j >> 1) * 8;
                    const int cc = c + (j & 1);
                    unsigned pos = atomicAdd(&g_cnt, 1u);
                    if (pos < CAP)
                        g_list[pos] = make_uint2((unsigned)rr * N_TOTAL + cc,
                                                 __float_as_uint(z[j]));
                }
            }
        }
    }
}

// ---------------- fixup kernel ----------------
__global__ void __launch_bounds__(256)
fixup(const float* __restrict__ x, float* __restrict__ out) {
    const unsigned total = min(g_cnt, CAP);
    const int lane   = threadIdx.x & 31;
    const int warpId = (blockIdx.x * blockDim.x + threadIdx.x) >> 5;
    const int nwarps = (gridDim.x * blockDim.x) >> 5;

    for (unsigned it = warpId; it < total; it += nwarps) {
        const uint2 e = g_list[it];
        const int m = e.x / N_TOTAL;
        const int n = e.x % N_TOTAL;
        const float zhi = __uint_as_float(e.y);

        const float4* xr = reinterpret_cast<const float4*>(x + (size_t)m * K_IN);
        const uint4*  wr = reinterpret_cast<const uint4*>(g_W + (size_t)n * K_IN);

        float s = 0.f;
        #pragma unroll 4
        for (int i = 0; i < 16; i++) {
            const int ch = i * 32 + lane;
            float4 x0 = xr[2 * ch];
            float4 x1 = xr[2 * ch + 1];
            uint4  wv = wr[ch];
            const __half2* wh = reinterpret_cast<const __half2*>(&wv);
            float xs[8] = {x0.x, x0.y, x0.z, x0.w, x1.x, x1.y, x1.z, x1.w};
            #pragma unroll
            for (int q = 0; q < 4; q++) {
                float2 wf = __half22float2(wh[q]);
                float xa = xs[2 * q], xb = xs[2 * q + 1];
                float la = xa - __half2float(__float2half_rn(xa));
                float lb = xb - __half2float(__float2half_rn(xb));
                s += la * wf.x + lb * wf.y;
            }
        }
        #pragma unroll
        for (int o = 16; o; o >>= 1) s += __shfl_xor_sync(0xffffffffu, s, o);
        if (lane == 0) out[e.x] = sgnf(zhi + s);
    }
}

// ---------------- host launch ----------------
extern "C" void kernel_launch(void* const* d_in, const int* in_sizes, int n_in,
                              void* d_out, int out_size) {
    const float* x    = (const float*)d_in[0];
    const float* w    = (const float*)d_in[1];
    const float* bias = (const float*)d_in[2];
    float* out = (float*)d_out;

    zero_cnt<<<1, 1>>>();
    prep_x<<<dim3(K_IN / (4 * 256), M_TOTAL), 256>>>(x);
    prep_w<<<(int)(((size_t)N_TOTAL * K_IN) / 4 / 256), 256>>>(w);

    cudaFuncSetAttribute(binlin_gemm, cudaFuncAttributeMaxDynamicSharedMemorySize,
                         SMEM_BYTES);
    binlin_gemm<<<dim3(N_TOTAL / BN, M_TOTAL / BM), 128, SMEM_BYTES>>>(bias, out);

    fixup<<<1024, 256>>>(x, out);
}

// round 9
// speedup vs baseline: 1.0922x; 1.0922x over previous
#include <cuda_runtime.h>
#include <cuda_fp16.h>
#include <cstdint>

// ---------------- problem constants ----------------
#define M_TOTAL 8192
#define N_TOTAL 4096
#define K_IN    4096

#define BM 128
#define BN 128
#define BKS 64                        // fp16 k-elems per stage
#define NK (K_IN / BKS)               // 64
#define STAGES 3
#define PITCH 72                      // smem row pitch in fp16 (64 data + 8 pad)
#define TILE_BYTES (128 * PITCH * 2)  // 18432 B per (A or B) stage tile
#define STAGE_BYTES (2 * TILE_BYTES)  // 36864
#define SMEM_BYTES (STAGES * STAGE_BYTES)  // 110592 (x2 CTAs = 221KB < 228KB)

#define TAU 0.125f
#define LCAP 1024                     // per-CTA worklist cap (expected ~25)

// ---------------- scratch ----------------
__device__ __half g_A[(size_t)M_TOTAL * K_IN];  // hi limb: fl16(x)
__device__ __half g_L[(size_t)M_TOTAL * K_IN];  // lo limb: fl16(x - hi)
__device__ __half g_W[(size_t)N_TOTAL * K_IN];  // sign(W) as fp16

// ---------------- helpers ----------------
static __device__ __forceinline__ void cpa16(uint32_t dst, const void* src) {
    asm volatile("cp.async.cg.shared.global [%0], [%1], 16;" :: "r"(dst), "l"(src));
}
static __device__ __forceinline__ void ldsm4(uint32_t* r, uint32_t addr) {
    asm volatile("ldmatrix.sync.aligned.m8n8.x4.shared.b16 {%0,%1,%2,%3}, [%4];"
                 : "=r"(r[0]), "=r"(r[1]), "=r"(r[2]), "=r"(r[3]) : "r"(addr));
}
static __device__ __forceinline__ void mma16816(float* c, const uint32_t* a, const uint32_t* b) {
    asm volatile(
        "mma.sync.aligned.m16n8k16.row.col.f32.f16.f16.f32 "
        "{%0,%1,%2,%3}, {%4,%5,%6,%7}, {%8,%9}, {%0,%1,%2,%3};"
        : "+f"(c[0]), "+f"(c[1]), "+f"(c[2]), "+f"(c[3])
        : "r"(a[0]), "r"(a[1]), "r"(a[2]), "r"(a[3]), "r"(b[0]), "r"(b[1]));
}
static __device__ __forceinline__ float sgnf(float z) {
    return (z > 0.f) ? 1.f : ((z < 0.f) ? -1.f : 0.f);
}

// ---------------- prep kernels ----------------
__global__ void prep_x(const float* __restrict__ x) {
    const int t   = blockIdx.x * blockDim.x + threadIdx.x;
    const int row = blockIdx.y;
    const int col = t * 4;
    float4 v = *reinterpret_cast<const float4*>(&x[(size_t)row * K_IN + col]);
    float vv[4] = {v.x, v.y, v.z, v.w};
    __half hi[4], lo[4];
    #pragma unroll
    for (int j = 0; j < 4; j++) {
        hi[j] = __float2half_rn(vv[j]);
        lo[j] = __float2half_rn(vv[j] - __half2float(hi[j]));
    }
    const size_t base = (size_t)row * K_IN + col;
    *reinterpret_cast<uint2*>(&g_A[base]) = *reinterpret_cast<uint2*>(hi);
    *reinterpret_cast<uint2*>(&g_L[base]) = *reinterpret_cast<uint2*>(lo);
}

__global__ void prep_w(const float* __restrict__ w) {
    const size_t idx = (size_t)blockIdx.x * blockDim.x + threadIdx.x;
    float4 v = *reinterpret_cast<const float4*>(&w[idx * 4]);
    float vv[4] = {v.x, v.y, v.z, v.w};
    __half s[4];
    #pragma unroll
    for (int j = 0; j < 4; j++) s[j] = __float2half_rn(sgnf(vv[j]));
    reinterpret_cast<uint2*>(g_W)[idx] = *reinterpret_cast<uint2*>(s);
}

// ---------------- GEMM kernel: hi-limb GEMM + inline exact fixup ----------------
__global__ void __launch_bounds__(256, 2)
binlin_gemm(const float* __restrict__ bias, float* __restrict__ out) {
    extern __shared__ __align__(16) char smem[];
    const uint32_t su = (uint32_t)__cvta_generic_to_shared(smem);

    const int tid  = threadIdx.x;
    const int wid  = tid >> 5;
    const int lane = tid & 31;
    const int wm = (wid >> 1) * 32;
    const int wn = (wid & 1) * 64;

    const int m_base = blockIdx.y * BM;
    const int n_base = blockIdx.x * BN;

    float acc[2][8][4];
    #pragma unroll
    for (int mi = 0; mi < 2; mi++)
        #pragma unroll
        for (int ni = 0; ni < 8; ni++)
            #pragma unroll
            for (int j = 0; j < 4; j++) acc[mi][ni][j] = 0.f;

    const int a_row_off = (lane & 7) + ((lane >> 3) & 1) * 8;
    const int a_col_off = (lane >> 4) * 8;
    const int b_row_off = (lane & 7) + (lane >> 4) * 8;
    const int b_col_off = ((lane >> 3) & 1) * 8;

    auto load_stage = [&](int s, int kk) {
        const uint32_t abase = su + s * STAGE_BYTES;
        const uint32_t bbase = abase + TILE_BYTES;
        const int ka = kk * BKS;
        #pragma unroll
        for (int i = 0; i < 4; i++) {
            const int cid = tid + i * 256;
            const int row = cid >> 3;
            const int c   = cid & 7;
            cpa16(abase + row * (PITCH * 2) + c * 16,
                  &g_A[(size_t)(m_base + row) * K_IN + ka + c * 8]);
            cpa16(bbase + row * (PITCH * 2) + c * 16,
                  &g_W[(size_t)(n_base + row) * K_IN + ka + c * 8]);
        }
    };

    auto compute_stage = [&](int s) {
        const uint32_t abase = su + s * STAGE_BYTES;
        const uint32_t bbase = abase + TILE_BYTES;
        #pragma unroll
        for (int ks = 0; ks < 4; ks++) {
            uint32_t a[2][4];
            uint32_t b[8][2];
            #pragma unroll
            for (int mi = 0; mi < 2; mi++) {
                uint32_t addr = abase +
                    ((wm + mi * 16 + a_row_off) * PITCH + ks * 16 + a_col_off) * 2;
                ldsm4(a[mi], addr);
            }
            #pragma unroll
            for (int p = 0; p < 4; p++) {
                uint32_t t[4];
                uint32_t addr = bbase +
                    ((wn + p * 16 + b_row_off) * PITCH + ks * 16 + b_col_off) * 2;
                ldsm4(t, addr);
                b[2 * p + 0][0] = t[0]; b[2 * p + 0][1] = t[1];
                b[2 * p + 1][0] = t[2]; b[2 * p + 1][1] = t[3];
            }
            #pragma unroll
            for (int mi = 0; mi < 2; mi++)
                #pragma unroll
                for (int ni = 0; ni < 8; ni++)
                    mma16816(acc[mi][ni], a[mi], b[ni]);
        }
    };

    // ---- prologue ----
    #pragma unroll
    for (int s = 0; s < STAGES - 1; s++) {
        load_stage(s, s);
        asm volatile("cp.async.commit_group;");
    }

    // ---- mainloop: one sync/iter, rotating stage indices (no modulo) ----
    int sc = 0;            // compute stage for kk
    int sl = STAGES - 1;   // load target stage for kk+STAGES-1
    for (int kk = 0; kk < NK; kk++) {
        asm volatile("cp.async.wait_group %0;" :: "n"(STAGES - 2));
        __syncthreads();
        if (kk + STAGES - 1 < NK) load_stage(sl, kk + STAGES - 1);
        asm volatile("cp.async.commit_group;");
        compute_stage(sc);
        sc = (sc + 1 == STAGES) ? 0 : sc + 1;
        sl = (sl + 1 == STAGES) ? 0 : sl + 1;
    }

    // ---- per-CTA worklist in smem (reuse stage memory after mainloop) ----
    unsigned* s_cnt = reinterpret_cast<unsigned*>(smem);
    unsigned* s_idx = reinterpret_cast<unsigned*>(smem + 16);
    float*    s_z   = reinterpret_cast<float*>(smem + 16 + LCAP * 4);
    __syncthreads();               // all warps done reading stage smem
    if (tid == 0) *s_cnt = 0u;
    __syncthreads();

    // ---- epilogue: provisional sign + flag near-zero outputs into smem ----
    #pragma unroll
    for (int mi = 0; mi < 2; mi++) {
        #pragma unroll
        for (int ni = 0; ni < 8; ni++) {
            const int r = m_base + wm + mi * 16 + (lane >> 2);
            const int c = n_base + wn + ni * 8 + (lane & 3) * 2;
            const float b0 = bias[c];
            const float b1 = bias[c + 1];
            float z[4];
            z[0] = acc[mi][ni][0] + b0;
            z[1] = acc[mi][ni][1] + b1;
            z[2] = acc[mi][ni][2] + b0;
            z[3] = acc[mi][ni][3] + b1;
            float2 v0, v1;
            v0.x = sgnf(z[0]); v0.y = sgnf(z[1]);
            v1.x = sgnf(z[2]); v1.y = sgnf(z[3]);
            *reinterpret_cast<float2*>(&out[(size_t)r * N_TOTAL + c]) = v0;
            *reinterpret_cast<float2*>(&out[(size_t)(r + 8) * N_TOTAL + c]) = v1;
            #pragma unroll
            for (int j = 0; j < 4; j++) {
                if (fabsf(z[j]) < TAU) {
                    const int rr = r + (j >> 1) * 8;
                    const int cc = c + (j & 1);
                    unsigned p = atomicAdd(s_cnt, 1u);
                    if (p < LCAP) {
                        s_idx[p] = (unsigned)rr * N_TOTAL + cc;
                        s_z[p]   = z[j];
                    }
                }
            }
        }
    }
    __syncthreads();

    // ---- inline fixup: warp-per-item exact lo-limb correction ----
    const unsigned total = min(*s_cnt, (unsigned)LCAP);
    for (unsigned it = wid; it < total; it += 8) {
        const unsigned idx = s_idx[it];
        const int m = idx >> 12;            // /4096
        const int n = idx & (N_TOTAL - 1);  // %4096
        const uint4* lr = reinterpret_cast<const uint4*>(g_L + (size_t)m * K_IN);
        const uint4* wr = reinterpret_cast<const uint4*>(g_W + (size_t)n * K_IN);
        float s = 0.f;
        #pragma unroll 4
        for (int i = 0; i < 16; i++) {
            const int ch = i * 32 + lane;   // 512 chunks of 8 halfs
            uint4 lv = lr[ch];
            uint4 wv = wr[ch];
            const __half2* lh = reinterpret_cast<const __half2*>(&lv);
            const __half2* wh = reinterpret_cast<const __half2*>(&wv);
            #pragma unroll
            for (int q = 0; q < 4; q++) {
                float2 lf = __half22float2(lh[q]);
                float2 wf = __half22float2(wh[q]);
                s += lf.x * wf.x + lf.y * wf.y;
            }
        }
        #pragma unroll
        for (int o = 16; o; o >>= 1) s += __shfl_xor_sync(0xffffffffu, s, o);
        if (lane == 0) out[idx] = sgnf(s_z[it] + s);
    }
}

// ---------------- host launch ----------------
extern "C" void kernel_launch(void* const* d_in, const int* in_sizes, int n_in,
                              void* d_out, int out_size) {
    const float* x    = (const float*)d_in[0];
    const float* w    = (const float*)d_in[1];
    const float* bias = (const float*)d_in[2];
    float* out = (float*)d_out;

    prep_x<<<dim3(K_IN / (4 * 256), M_TOTAL), 256>>>(x);
    prep_w<<<(int)(((size_t)N_TOTAL * K_IN) / 4 / 256), 256>>>(w);

    cudaFuncSetAttribute(binlin_gemm, cudaFuncAttributeMaxDynamicSharedMemorySize,
                         SMEM_BYTES);
    binlin_gemm<<<dim3(N_TOTAL / BN, M_TOTAL / BM), 256, SMEM_BYTES>>>(bias, out);
}

// round 10
// speedup vs baseline: 1.1918x; 1.0911x over previous
#include <cuda_runtime.h>
#include <cuda_fp16.h>
#include <cstdint>

// ---------------- problem constants ----------------
#define M_TOTAL 8192
#define N_TOTAL 4096
#define K_IN    4096

#define BM 128
#define BN 128
#define BKS 64                        // fp16 k-elems per stage
#define NK (K_IN / BKS)               // 64
#define STAGES 3
#define PITCH 72                      // smem row pitch in fp16 (64 data + 8 pad)
#define TILE_BYTES (128 * PITCH * 2)  // 18432 B per (A or B) stage tile
#define STAGE_BYTES (2 * TILE_BYTES)  // 36864
#define SMEM_BYTES (STAGES * STAGE_BYTES)  // 110592 (x2 CTAs = 221KB < 228KB)

#define TAU 0.125f
#define LCAP 1024                     // per-CTA worklist cap (expected ~25)

#define NXV ((size_t)M_TOTAL * K_IN / 4)   // x float4 count: 8.39M
#define NWV ((size_t)N_TOTAL * K_IN / 4)   // w float4 count: 4.19M

// ---------------- scratch ----------------
__device__ __half g_A[(size_t)M_TOTAL * K_IN];  // hi limb: fl16(x)
__device__ __half g_L[(size_t)M_TOTAL * K_IN];  // lo limb: fl16(x - hi)
__device__ __half g_W[(size_t)N_TOTAL * K_IN];  // sign(W) as fp16

// ---------------- helpers ----------------
static __device__ __forceinline__ void cpa16(uint32_t dst, const void* src) {
    asm volatile("cp.async.cg.shared.global [%0], [%1], 16;" :: "r"(dst), "l"(src));
}
static __device__ __forceinline__ void ldsm4(uint32_t* r, uint32_t addr) {
    asm volatile("ldmatrix.sync.aligned.m8n8.x4.shared.b16 {%0,%1,%2,%3}, [%4];"
                 : "=r"(r[0]), "=r"(r[1]), "=r"(r[2]), "=r"(r[3]) : "r"(addr));
}
static __device__ __forceinline__ void mma16816(float* c, const uint32_t* a, const uint32_t* b) {
    asm volatile(
        "mma.sync.aligned.m16n8k16.row.col.f32.f16.f16.f32 "
        "{%0,%1,%2,%3}, {%4,%5,%6,%7}, {%8,%9}, {%0,%1,%2,%3};"
        : "+f"(c[0]), "+f"(c[1]), "+f"(c[2]), "+f"(c[3])
        : "r"(a[0]), "r"(a[1]), "r"(a[2]), "r"(a[3]), "r"(b[0]), "r"(b[1]));
}
static __device__ __forceinline__ float sgnf(float z) {
    return (z > 0.f) ? 1.f : ((z < 0.f) ? -1.f : 0.f);
}

// ---------------- merged prep kernel ----------------
__global__ void prep_all(const float* __restrict__ x, const float* __restrict__ w) {
    const size_t i = (size_t)blockIdx.x * blockDim.x + threadIdx.x;
    if (i < NXV) {
        float4 v = reinterpret_cast<const float4*>(x)[i];
        float vv[4] = {v.x, v.y, v.z, v.w};
        __half hi[4], lo[4];
        #pragma unroll
        for (int j = 0; j < 4; j++) {
            hi[j] = __float2half_rn(vv[j]);
            lo[j] = __float2half_rn(vv[j] - __half2float(hi[j]));
        }
        reinterpret_cast<uint2*>(g_A)[i] = *reinterpret_cast<uint2*>(hi);
        reinterpret_cast<uint2*>(g_L)[i] = *reinterpret_cast<uint2*>(lo);
    } else {
        const size_t k = i - NXV;
        if (k < NWV) {
            float4 v = reinterpret_cast<const float4*>(w)[k];
            float vv[4] = {v.x, v.y, v.z, v.w};
            __half s[4];
            #pragma unroll
            for (int j = 0; j < 4; j++) s[j] = __float2half_rn(sgnf(vv[j]));
            reinterpret_cast<uint2*>(g_W)[k] = *reinterpret_cast<uint2*>(s);
        }
    }
}

// ---------------- GEMM kernel: hi-limb GEMM + inline exact fixup ----------------
__global__ void __launch_bounds__(256, 2)
binlin_gemm(const float* __restrict__ bias, float* __restrict__ out) {
    extern __shared__ __align__(16) char smem[];
    const uint32_t su = (uint32_t)__cvta_generic_to_shared(smem);

    const int tid  = threadIdx.x;
    const int wid  = tid >> 5;
    const int lane = tid & 31;
    const int wm = (wid >> 1) * 32;
    const int wn = (wid & 1) * 64;

    const int m_base = blockIdx.y * BM;
    const int n_base = blockIdx.x * BN;

    float acc[2][8][4];
    #pragma unroll
    for (int mi = 0; mi < 2; mi++)
        #pragma unroll
        for (int ni = 0; ni < 8; ni++)
            #pragma unroll
            for (int j = 0; j < 4; j++) acc[mi][ni][j] = 0.f;

    const int a_row_off = (lane & 7) + ((lane >> 3) & 1) * 8;
    const int a_col_off = (lane >> 4) * 8;
    const int b_row_off = (lane & 7) + (lane >> 4) * 8;
    const int b_col_off = ((lane >> 3) & 1) * 8;

    auto load_stage = [&](int s, int kk) {
        const uint32_t abase = su + s * STAGE_BYTES;
        const uint32_t bbase = abase + TILE_BYTES;
        const int ka = kk * BKS;
        #pragma unroll
        for (int i = 0; i < 4; i++) {
            const int cid = tid + i * 256;
            const int row = cid >> 3;
            const int c   = cid & 7;
            cpa16(abase + row * (PITCH * 2) + c * 16,
                  &g_A[(size_t)(m_base + row) * K_IN + ka + c * 8]);
            cpa16(bbase + row * (PITCH * 2) + c * 16,
                  &g_W[(size_t)(n_base + row) * K_IN + ka + c * 8]);
        }
    };

    // one K=16 slice of the stage
    auto compute_ks = [&](int s, int ks) {
        const uint32_t abase = su + s * STAGE_BYTES;
        const uint32_t bbase = abase + TILE_BYTES;
        uint32_t a[2][4];
        uint32_t b[8][2];
        #pragma unroll
        for (int mi = 0; mi < 2; mi++) {
            uint32_t addr = abase +
                ((wm + mi * 16 + a_row_off) * PITCH + ks * 16 + a_col_off) * 2;
            ldsm4(a[mi], addr);
        }
        #pragma unroll
        for (int p = 0; p < 4; p++) {
            uint32_t t[4];
            uint32_t addr = bbase +
                ((wn + p * 16 + b_row_off) * PITCH + ks * 16 + b_col_off) * 2;
            ldsm4(t, addr);
            b[2 * p + 0][0] = t[0]; b[2 * p + 0][1] = t[1];
            b[2 * p + 1][0] = t[2]; b[2 * p + 1][1] = t[3];
        }
        #pragma unroll
        for (int mi = 0; mi < 2; mi++)
            #pragma unroll
            for (int ni = 0; ni < 8; ni++)
                mma16816(acc[mi][ni], a[mi], b[ni]);
    };

    // one mainloop step with compile-time stage indices:
    // wait -> sync -> HMMA ks0 -> issue next loads -> commit -> HMMA ks1..3
    auto step = [&](int kk, int sc, int sl) {
        asm volatile("cp.async.wait_group %0;" :: "n"(STAGES - 2));
        __syncthreads();
        compute_ks(sc, 0);
        if (kk + STAGES - 1 < NK) load_stage(sl, kk + STAGES - 1);
        asm volatile("cp.async.commit_group;");
        compute_ks(sc, 1);
        compute_ks(sc, 2);
        compute_ks(sc, 3);
    };

    // ---- prologue ----
    #pragma unroll
    for (int s = 0; s < STAGES - 1; s++) {
        load_stage(s, s);
        asm volatile("cp.async.commit_group;");
    }

    // ---- mainloop: unrolled by the stage period (3) ----
    for (int kt = 0; kt < 21; kt++) {
        const int kk = kt * 3;
        step(kk + 0, 0, 2);
        step(kk + 1, 1, 0);
        step(kk + 2, 2, 1);
    }
    step(63, 0, 2);   // tail (63 % 3 == 0)

    // ---- per-CTA worklist in smem (reuse stage memory after mainloop) ----
    unsigned* s_cnt = reinterpret_cast<unsigned*>(smem);
    unsigned* s_idx = reinterpret_cast<unsigned*>(smem + 16);
    float*    s_z   = reinterpret_cast<float*>(smem + 16 + LCAP * 4);
    __syncthreads();
    if (tid == 0) *s_cnt = 0u;
    __syncthreads();

    // ---- epilogue: provisional sign + flag near-zero outputs ----
    #pragma unroll
    for (int mi = 0; mi < 2; mi++) {
        #pragma unroll
        for (int ni = 0; ni < 8; ni++) {
            const int r = m_base + wm + mi * 16 + (lane >> 2);
            const int c = n_base + wn + ni * 8 + (lane & 3) * 2;
            const float b0 = bias[c];
            const float b1 = bias[c + 1];
            float z[4];
            z[0] = acc[mi][ni][0] + b0;
            z[1] = acc[mi][ni][1] + b1;
            z[2] = acc[mi][ni][2] + b0;
            z[3] = acc[mi][ni][3] + b1;
            float2 v0, v1;
            v0.x = sgnf(z[0]); v0.y = sgnf(z[1]);
            v1.x = sgnf(z[2]); v1.y = sgnf(z[3]);
            *reinterpret_cast<float2*>(&out[(size_t)r * N_TOTAL + c]) = v0;
            *reinterpret_cast<float2*>(&out[(size_t)(r + 8) * N_TOTAL + c]) = v1;
            #pragma unroll
            for (int j = 0; j < 4; j++) {
                if (fabsf(z[j]) < TAU) {
                    const int rr = r + (j >> 1) * 8;
                    const int cc = c + (j & 1);
                    unsigned p = atomicAdd(s_cnt, 1u);
                    if (p < LCAP) {
                        s_idx[p] = (unsigned)rr * N_TOTAL + cc;
                        s_z[p]   = z[j];
                    }
                }
            }
        }
    }
    __syncthreads();

    // ---- inline fixup: warp-per-item exact lo-limb correction ----
    const unsigned total = min(*s_cnt, (unsigned)LCAP);
    for (unsigned it = wid; it < total; it += 8) {
        const unsigned idx = s_idx[it];
        const int m = idx >> 12;
        const int n = idx & (N_TOTAL - 1);
        const uint4* lr = reinterpret_cast<const uint4*>(g_L + (size_t)m * K_IN);
        const uint4* wr = reinterpret_cast<const uint4*>(g_W + (size_t)n * K_IN);
        float s = 0.f;
        #pragma unroll 4
        for (int i = 0; i < 16; i++) {
            const int ch = i * 32 + lane;
            uint4 lv = lr[ch];
            uint4 wv = wr[ch];
            const __half2* lh = reinterpret_cast<const __half2*>(&lv);
            const __half2* wh = reinterpret_cast<const __half2*>(&wv);
            #pragma unroll
            for (int q = 0; q < 4; q++) {
                float2 lf = __half22float2(lh[q]);
                float2 wf = __half22float2(wh[q]);
                s += lf.x * wf.x + lf.y * wf.y;
            }
        }
        #pragma unroll
        for (int o = 16; o; o >>= 1) s += __shfl_xor_sync(0xffffffffu, s, o);
        if (lane == 0) out[idx] = sgnf(s_z[it] + s);
    }
}

// ---------------- host launch ----------------
extern "C" void kernel_launch(void* const* d_in, const int* in_sizes, int n_in,
                              void* d_out, int out_size) {
    const float* x    = (const float*)d_in[0];
    const float* w    = (const float*)d_in[1];
    const float* bias = (const float*)d_in[2];
    float* out = (float*)d_out;

    const int nv = (int)((NXV + NWV + 255) / 256);
    prep_all<<<nv, 256>>>(x, w);

    cudaFuncSetAttribute(binlin_gemm, cudaFuncAttributeMaxDynamicSharedMemorySize,
                         SMEM_BYTES);
    binlin_gemm<<<dim3(N_TOTAL / BN, M_TOTAL / BM), 256, SMEM_BYTES>>>(bias, out);
}

// round 11
// speedup vs baseline: 1.2948x; 1.0865x over previous
#include <cuda_runtime.h>
#include <cuda_fp16.h>
#include <cstdint>

// ---------------- problem constants ----------------
#define M_TOTAL 8192
#define N_TOTAL 4096
#define K_IN    4096

#define BM 128
#define BN 128
#define BKS 64                        // fp16 k-elems per stage
#define NK (K_IN / BKS)               // 64
#define STAGES 3
#define PITCH 72                      // smem row pitch in fp16 (64 data + 8 pad)
#define TILE_BYTES (128 * PITCH * 2)  // 18432 B per (A or B) stage tile
#define STAGE_BYTES (2 * TILE_BYTES)  // 36864
#define SMEM_BYTES (STAGES * STAGE_BYTES)  // 110592 (x2 CTAs = 221KB < 228KB)

#define TAU 0.125f
#define LCAP 1024

#define NXV ((size_t)M_TOTAL * K_IN / 4)
#define NWV ((size_t)N_TOTAL * K_IN / 4)

// ---------------- scratch ----------------
__device__ __half g_A[(size_t)M_TOTAL * K_IN];  // hi limb: fl16(x)
__device__ __half g_L[(size_t)M_TOTAL * K_IN];  // lo limb: fl16(x - hi)
__device__ __half g_W[(size_t)N_TOTAL * K_IN];  // sign(W) as fp16

// ---------------- helpers ----------------
static __device__ __forceinline__ void cpa16(uint32_t dst, const void* src) {
    asm volatile("cp.async.cg.shared.global [%0], [%1], 16;" :: "r"(dst), "l"(src));
}
static __device__ __forceinline__ void ldsm4(uint32_t* r, uint32_t addr) {
    asm volatile("ldmatrix.sync.aligned.m8n8.x4.shared.b16 {%0,%1,%2,%3}, [%4];"
                 : "=r"(r[0]), "=r"(r[1]), "=r"(r[2]), "=r"(r[3]) : "r"(addr));
}
static __device__ __forceinline__ void mma16816(float* c, const uint32_t* a, const uint32_t* b) {
    asm volatile(
        "mma.sync.aligned.m16n8k16.row.col.f32.f16.f16.f32 "
        "{%0,%1,%2,%3}, {%4,%5,%6,%7}, {%8,%9}, {%0,%1,%2,%3};"
        : "+f"(c[0]), "+f"(c[1]), "+f"(c[2]), "+f"(c[3])
        : "r"(a[0]), "r"(a[1]), "r"(a[2]), "r"(a[3]), "r"(b[0]), "r"(b[1]));
}
static __device__ __forceinline__ float sgnf(float z) {
    return (z > 0.f) ? 1.f : ((z < 0.f) ? -1.f : 0.f);
}

// ---------------- merged prep kernel ----------------
__global__ void prep_all(const float* __restrict__ x, const float* __restrict__ w) {
    const size_t i = (size_t)blockIdx.x * blockDim.x + threadIdx.x;
    if (i < NXV) {
        float4 v = reinterpret_cast<const float4*>(x)[i];
        float vv[4] = {v.x, v.y, v.z, v.w};
        __half hi[4], lo[4];
        #pragma unroll
        for (int j = 0; j < 4; j++) {
            hi[j] = __float2half_rn(vv[j]);
            lo[j] = __float2half_rn(vv[j] - __half2float(hi[j]));
        }
        reinterpret_cast<uint2*>(g_A)[i] = *reinterpret_cast<uint2*>(hi);
        reinterpret_cast<uint2*>(g_L)[i] = *reinterpret_cast<uint2*>(lo);
    } else {
        const size_t k = i - NXV;
        if (k < NWV) {
            float4 v = reinterpret_cast<const float4*>(w)[k];
            float vv[4] = {v.x, v.y, v.z, v.w};
            __half s[4];
            #pragma unroll
            for (int j = 0; j < 4; j++) s[j] = __float2half_rn(sgnf(vv[j]));
            reinterpret_cast<uint2*>(g_W)[k] = *reinterpret_cast<uint2*>(s);
        }
    }
}

// ---------------- GEMM kernel ----------------
__global__ void __launch_bounds__(256, 2)
binlin_gemm(const float* __restrict__ bias, float* __restrict__ out) {
    extern __shared__ __align__(16) char smem[];
    const uint32_t su = (uint32_t)__cvta_generic_to_shared(smem);

    const int tid  = threadIdx.x;
    const int wid  = tid >> 5;
    const int lane = tid & 31;
    const int wm = (wid >> 1) * 32;
    const int wn = (wid & 1) * 64;

    const int m_base = blockIdx.y * BM;
    const int n_base = blockIdx.x * BN;

    float acc[2][8][4];
    #pragma unroll
    for (int mi = 0; mi < 2; mi++)
        #pragma unroll
        for (int ni = 0; ni < 8; ni++)
            #pragma unroll
            for (int j = 0; j < 4; j++) acc[mi][ni][j] = 0.f;

    const int a_row_off = (lane & 7) + ((lane >> 3) & 1) * 8;
    const int a_col_off = (lane >> 4) * 8;
    const int b_row_off = (lane & 7) + (lane >> 4) * 8;
    const int b_col_off = ((lane >> 3) & 1) * 8;

    // one 8-cpa chunk (quarter) of a stage load
    auto load_chunk = [&](int s, int kk, int i) {
        const uint32_t abase = su + s * STAGE_BYTES;
        const uint32_t bbase = abase + TILE_BYTES;
        const int ka = kk * BKS;
        const int cid = tid + i * 256;
        const int row = cid >> 3;
        const int c   = cid & 7;
        cpa16(abase + row * (PITCH * 2) + c * 16,
              &g_A[(size_t)(m_base + row) * K_IN + ka + c * 8]);
        cpa16(bbase + row * (PITCH * 2) + c * 16,
              &g_W[(size_t)(n_base + row) * K_IN + ka + c * 8]);
    };
    auto load_stage = [&](int s, int kk) {
        #pragma unroll
        for (int i = 0; i < 4; i++) load_chunk(s, kk, i);
    };

    // LDSM one K=16 slice into given fragment registers
    auto ldsm_ks = [&](int s, int ks, uint32_t a[2][4], uint32_t b[8][2]) {
        const uint32_t abase = su + s * STAGE_BYTES;
        const uint32_t bbase = abase + TILE_BYTES;
        #pragma unroll
        for (int mi = 0; mi < 2; mi++) {
            uint32_t addr = abase +
                ((wm + mi * 16 + a_row_off) * PITCH + ks * 16 + a_col_off) * 2;
            ldsm4(a[mi], addr);
        }
        #pragma unroll
        for (int p = 0; p < 4; p++) {
            uint32_t t[4];
            uint32_t addr = bbase +
                ((wn + p * 16 + b_row_off) * PITCH + ks * 16 + b_col_off) * 2;
            ldsm4(t, addr);
            b[2 * p + 0][0] = t[0]; b[2 * p + 0][1] = t[1];
            b[2 * p + 1][0] = t[2]; b[2 * p + 1][1] = t[3];
        }
    };
    auto mma_all = [&](uint32_t a[2][4], uint32_t b[8][2]) {
        #pragma unroll
        for (int mi = 0; mi < 2; mi++)
            #pragma unroll
            for (int ni = 0; ni < 8; ni++)
                mma16816(acc[mi][ni], a[mi], b[ni]);
    };

    // one step: fragment-pipelined slices + spread loads; commit at step end
    auto step = [&](int kk, int sc, int sl) {
        asm volatile("cp.async.wait_group %0;" :: "n"(STAGES - 2));
        __syncthreads();
        const bool ld = (kk + STAGES - 1 < NK);
        uint32_t a0[2][4], b0[8][2], a1[2][4], b1[8][2];
        ldsm_ks(sc, 0, a0, b0);
        if (ld) load_chunk(sl, kk + STAGES - 1, 0);
        ldsm_ks(sc, 1, a1, b1);
        mma_all(a0, b0);
        if (ld) load_chunk(sl, kk + STAGES - 1, 1);
        ldsm_ks(sc, 2, a0, b0);
        mma_all(a1, b1);
        if (ld) load_chunk(sl, kk + STAGES - 1, 2);
        ldsm_ks(sc, 3, a1, b1);
        mma_all(a0, b0);
        if (ld) load_chunk(sl, kk + STAGES - 1, 3);
        asm volatile("cp.async.commit_group;");
        mma_all(a1, b1);
    };

    // ---- prologue ----
    #pragma unroll
    for (int s = 0; s < STAGES - 1; s++) {
        load_stage(s, s);
        asm volatile("cp.async.commit_group;");
    }

    // ---- mainloop: unrolled by the stage period (3) ----
    for (int kt = 0; kt < 21; kt++) {
        const int kk = kt * 3;
        step(kk + 0, 0, 2);
        step(kk + 1, 1, 0);
        step(kk + 2, 2, 1);
    }
    step(63, 0, 2);   // tail (63 % 3 == 0)

    // ---- per-CTA worklist in smem ----
    unsigned* s_cnt = reinterpret_cast<unsigned*>(smem);
    unsigned* s_idx = reinterpret_cast<unsigned*>(smem + 16);
    float*    s_z   = reinterpret_cast<float*>(smem + 16 + LCAP * 4);
    __syncthreads();
    if (tid == 0) *s_cnt = 0u;
    __syncthreads();

    // ---- epilogue: provisional sign + flag near-zero outputs ----
    #pragma unroll
    for (int mi = 0; mi < 2; mi++) {
        #pragma unroll
        for (int ni = 0; ni < 8; ni++) {
            const int r = m_base + wm + mi * 16 + (lane >> 2);
            const int c = n_base + wn + ni * 8 + (lane & 3) * 2;
            const float b0 = bias[c];
            const float b1 = bias[c + 1];
            float z[4];
            z[0] = acc[mi][ni][0] + b0;
            z[1] = acc[mi][ni][1] + b1;
            z[2] = acc[mi][ni][2] + b0;
            z[3] = acc[mi][ni][3] + b1;
            float2 v0, v1;
            v0.x = sgnf(z[0]); v0.y = sgnf(z[1]);
            v1.x = sgnf(z[2]); v1.y = sgnf(z[3]);
            *reinterpret_cast<float2*>(&out[(size_t)r * N_TOTAL + c]) = v0;
            *reinterpret_cast<float2*>(&out[(size_t)(r + 8) * N_TOTAL + c]) = v1;
            #pragma unroll
            for (int j = 0; j < 4; j++) {
                if (fabsf(z[j]) < TAU) {
                    const int rr = r + (j >> 1) * 8;
                    const int cc = c + (j & 1);
                    unsigned p = atomicAdd(s_cnt, 1u);
                    if (p < LCAP) {
                        s_idx[p] = (unsigned)rr * N_TOTAL + cc;
                        s_z[p]   = z[j];
                    }
                }
            }
        }
    }
    __syncthreads();

    // ---- inline fixup: warp-per-item exact lo-limb correction ----
    const unsigned total = min(*s_cnt, (unsigned)LCAP);
    for (unsigned it = wid; it < total; it += 8) {
        const unsigned idx = s_idx[it];
        const int m = idx >> 12;
        const int n = idx & (N_TOTAL - 1);
        const uint4* lr = reinterpret_cast<const uint4*>(g_L + (size_t)m * K_IN);
        const uint4* wr = reinterpret_cast<const uint4*>(g_W + (size_t)n * K_IN);
        float s = 0.f;
        #pragma unroll 4
        for (int i = 0; i < 16; i++) {
            const int ch = i * 32 + lane;
            uint4 lv = lr[ch];
            uint4 wv = wr[ch];
            const __half2* lh = reinterpret_cast<const __half2*>(&lv);
            const __half2* wh = reinterpret_cast<const __half2*>(&wv);
            #pragma unroll
            for (int q = 0; q < 4; q++) {
                float2 lf = __half22float2(lh[q]);
                float2 wf = __half22float2(wh[q]);
                s += lf.x * wf.x + lf.y * wf.y;
            }
        }
        #pragma unroll
        for (int o = 16; o; o >>= 1) s += __shfl_xor_sync(0xffffffffu, s, o);
        if (lane == 0) out[idx] = sgnf(s_z[it] + s);
    }
}

// ---------------- host launch ----------------
extern "C" void kernel_launch(void* const* d_in, const int* in_sizes, int n_in,
                              void* d_out, int out_size) {
    const float* x    = (const float*)d_in[0];
    const float* w    = (const float*)d_in[1];
    const float* bias = (const float*)d_in[2];
    float* out = (float*)d_out;

    const int nv = (int)((NXV + NWV + 255) / 256);
    prep_all<<<nv, 256>>>(x, w);

    cudaFuncSetAttribute(binlin_gemm, cudaFuncAttributeMaxDynamicSharedMemorySize,
                         SMEM_BYTES);
    binlin_gemm<<<dim3(N_TOTAL / BN, M_TOTAL / BM), 256, SMEM_BYTES>>>(bias, out);
}